// round 11
// baseline (speedup 1.0000x reference)
#include <cuda_runtime.h>
#include <cuda_bf16.h>
#include <cstdint>
#include <math.h>

// ---------------- problem constants ----------------
#define Bsz   1024
#define Tlen  80
#define Dd    512
#define Cc    78
#define Mrows (Bsz*Tlen)          // 81920
#define BLANKI 77
#define PRED  30
#define LOGITS_ELEMS ((size_t)Mrows * Cc)

// ---------------- tiling ----------------
#define RT    128                 // rows per CTA
#define NTHR  256                 // 8 warps: 4 m-warps x 2 n-warps
#define BK    16                  // K per chunk (1 mma k-step)
#define NCH   (Dd/BK)             // 32 chunks
#define AROW  24                  // bf16 row stride (16 data + 8 pad; 48B, 16B-aligned, conflict-free)
#define BROW  24
#define APL   (RT*AROW*2)         // A plane bytes = 6144
#define BPL   (80*BROW*2)         // B plane bytes = 3840
#define BOFF  (3*APL)             // 18432
#define STAGE (BOFF + 3*BPL)      // 29952
#define SMEM_BYTES (2*STAGE)      // 59904 (>= 128*84*4 = 43008 epilogue bytes); 3 CTAs/SM fits
#define LP    84                  // epilogue logits row stride (floats)

// ---------------- device scratch (static, no runtime alloc) ----------------
__device__ int  g_best[Mrows];
__device__ __nv_bfloat16 g_Ws[3][80][Dd];   // W^T limbs: [limb][n][k]

// ---------------- helpers ----------------
__device__ __forceinline__ void split3(float v, __nv_bfloat16& h0,
                                       __nv_bfloat16& h1, __nv_bfloat16& h2) {
    h0 = __float2bfloat16_rn(v);
    float r1 = v - __bfloat162float(h0);
    h1 = __float2bfloat16_rn(r1);
    float r2 = r1 - __bfloat162float(h1);
    h2 = __float2bfloat16_rn(r2);
}

// paired split: (x,y) -> 3 packed bf16x2 limbs
__device__ __forceinline__ void split3x2(float x, float y,
                                         uint32_t& p0, uint32_t& p1, uint32_t& p2) {
    __nv_bfloat162 h0 = __float22bfloat162_rn(make_float2(x, y));
    float2 f0 = __bfloat1622float2(h0);
    float rx = x - f0.x, ry = y - f0.y;
    __nv_bfloat162 h1 = __float22bfloat162_rn(make_float2(rx, ry));
    float2 f1 = __bfloat1622float2(h1);
    __nv_bfloat162 h2 = __float22bfloat162_rn(make_float2(rx - f1.x, ry - f1.y));
    p0 = *reinterpret_cast<uint32_t*>(&h0);
    p1 = *reinterpret_cast<uint32_t*>(&h1);
    p2 = *reinterpret_cast<uint32_t*>(&h2);
}

__device__ __forceinline__ void mma16816(float c[4], const uint32_t a[4],
                                         const uint32_t b[2]) {
    asm volatile(
        "mma.sync.aligned.m16n8k16.row.col.f32.bf16.bf16.f32 "
        "{%0,%1,%2,%3}, {%4,%5,%6,%7}, {%8,%9}, {%0,%1,%2,%3};"
        : "+f"(c[0]), "+f"(c[1]), "+f"(c[2]), "+f"(c[3])
        : "r"(a[0]), "r"(a[1]), "r"(a[2]), "r"(a[3]), "r"(b[0]), "r"(b[1]));
}

#define LDMX4(r, addr) \
    asm volatile("ldmatrix.sync.aligned.m8n8.x4.shared.b16 {%0,%1,%2,%3}, [%4];" \
        : "=r"((r)[0]), "=r"((r)[1]), "=r"((r)[2]), "=r"((r)[3]) : "r"(addr))
#define LDMX4P(r0, r1, addr) \
    asm volatile("ldmatrix.sync.aligned.m8n8.x4.shared.b16 {%0,%1,%2,%3}, [%4];" \
        : "=r"((r0)[0]), "=r"((r0)[1]), "=r"((r1)[0]), "=r"((r1)[1]) : "r"(addr))
#define LDMX2(r, addr) \
    asm volatile("ldmatrix.sync.aligned.m8n8.x2.shared.b16 {%0,%1}, [%2];" \
        : "=r"((r)[0]), "=r"((r)[1]) : "r"(addr))

__device__ __forceinline__ void cp_async16(uint32_t dst_smem, const void* src) {
    asm volatile("cp.async.cg.shared.global [%0], [%1], 16;" :: "r"(dst_smem), "l"(src));
}
#define CP_COMMIT() asm volatile("cp.async.commit_group;" ::: "memory")
#define CP_WAIT0()  asm volatile("cp.async.wait_group 0;" ::: "memory")

// ---------------- W prep: transpose + 3-way bf16 split ----------------
__global__ void prep_w(const float* __restrict__ Wm) {
    int i = blockIdx.x * blockDim.x + threadIdx.x;   // n*512 + k
    if (i >= 80 * Dd) return;
    int n = i >> 9, k = i & 511;
    float v = (n < Cc) ? Wm[(size_t)k * Cc + n] : 0.0f;
    __nv_bfloat16 h0, h1, h2;
    split3(v, h0, h1, h2);
    g_Ws[0][n][k] = h0; g_Ws[1][n][k] = h1; g_Ws[2][n][k] = h2;
}

// ---------------- fused mma GEMM + softmax + argmax ----------------
// CTA tile 128x80, 8 warps as (wm 0..3) x (wn 0..1): warp tile 32x40.
// Per chunk: one k16-step of 6 limb passes {a0b0,a1b0,a2b0,a0b1,a1b1,a0b2}.
__global__ __launch_bounds__(NTHR, 3)
void gemm_mma_kernel(const float* __restrict__ feat,
                     const float* __restrict__ bias,
                     float* __restrict__ out)
{
    extern __shared__ char dsm[];
    __shared__ float bias_s[80];
    __shared__ float rinv_s[RT];

    const int t    = threadIdx.x;
    const int lane = t & 31;
    const int wid  = t >> 5;
    const int wm   = wid & 3;
    const int wn   = wid >> 2;
    const int gID  = lane >> 2;
    const int tid4 = lane & 3;
    const int m0   = blockIdx.x * RT;
    const uint32_t dsmu = (uint32_t)__cvta_generic_to_shared(dsm);

    if (t < 80) bias_s[t] = (t < Cc) ? bias[t] : 0.0f;

    // ldmatrix per-lane address offsets (within plane)
    const uint32_t aoff0 = (uint32_t)((wm * 32 + (lane & 15)) * (AROW * 2) + (lane >> 4) * 16);
    const uint32_t aoff1 = aoff0 + 16 * (AROW * 2);
    const uint32_t boff0 = (uint32_t)((wn * 40 + (lane >> 4) * 8 + (lane & 7)) * (BROW * 2)
                                      + ((lane >> 3) & 1) * 16);
    const uint32_t boff2 = boff0 + 16 * (BROW * 2);
    const uint32_t boff4 = (uint32_t)((wn * 40 + 32 + (lane & 7)) * (BROW * 2)
                                      + ((lane >> 3) & 1) * 16);

    float acc[2][5][4];
#pragma unroll
    for (int i = 0; i < 2; i++)
#pragma unroll
        for (int j = 0; j < 5; j++)
#pragma unroll
            for (int q = 0; q < 4; q++) acc[i][j][q] = 0.0f;

    const float* featb = feat + (size_t)m0 * Dd;

    // ---- A store: split fp32 float4 -> 3 bf16 planes (one STS.64 per plane) ----
    auto storeA = [&](char* aB, int fidx, float4 v) {
        const int r = fidx >> 2, q = fidx & 3;       // 4 float4 per 16-float row
        const int off = r * (AROW * 2) + q * 8;
        uint2 u0, u1, u2;
        split3x2(v.x, v.y, u0.x, u1.x, u2.x);
        split3x2(v.z, v.w, u0.y, u1.y, u2.y);
        *(uint2*)(aB + 0 * APL + off) = u0;
        *(uint2*)(aB + 1 * APL + off) = u1;
        *(uint2*)(aB + 2 * APL + off) = u2;
    };

    // ---- B load: 480 x 16B per chunk via cp.async ----
    auto loadB = [&](uint32_t bBu, int kb) {
#pragma unroll
        for (int i = 0; i < 2; i++) {
            const int idx = t + NTHR * i;            // 0..511, use 0..479
            if (idx < 480) {
                const int p = idx / 160, rem = idx - p * 160;
                const int n = rem >> 1, q = rem & 1;
                cp_async16(bBu + p * BPL + n * (BROW * 2) + q * 16,
                           &g_Ws[p][n][kb + q * 8]);
            }
        }
    };

    // ---- prologue: chunk 0 ----
    {
        loadB(dsmu + BOFF, 0);
        CP_COMMIT();
#pragma unroll
        for (int i = 0; i < 2; i++) {
            const int fidx = t + NTHR * i;           // 0..511
            const int r = fidx >> 2, q = fidx & 3;
            float4 v = *reinterpret_cast<const float4*>(featb + (size_t)r * Dd + q * 4);
            storeA(dsm, fidx, v);
        }
        CP_WAIT0();
    }
    __syncthreads();

    // ---- main loop: 32 chunks ----
    for (int ch = 0; ch < NCH; ++ch) {
        const int s = ch & 1;
        const uint32_t aBu = dsmu + s * STAGE;
        const uint32_t bBu = aBu + BOFF;

        float4 pf[2];
        if (ch < NCH - 1) {
            const int kb = (ch + 1) * BK;
#pragma unroll
            for (int i = 0; i < 2; i++) {
                const int fidx = t + NTHR * i;
                const int r = fidx >> 2, q = fidx & 3;
                pf[i] = *reinterpret_cast<const float4*>(featb + (size_t)r * Dd + kb + q * 4);
            }
            loadB(dsmu + (s ^ 1) * STAGE + BOFF, kb);
            CP_COMMIT();
        }

        // ---- one k16-step of 6-pass limb mma (ldmatrix fragments) ----
        {
            uint32_t afr[3][2][4];
#pragma unroll
            for (int ai = 0; ai < 3; ai++) {
                LDMX4(afr[ai][0], aBu + ai * APL + aoff0);
                LDMX4(afr[ai][1], aBu + ai * APL + aoff1);
            }
#pragma unroll
            for (int bj = 0; bj < 3; bj++) {
                uint32_t b[5][2];
                LDMX4P(b[0], b[1], bBu + bj * BPL + boff0);
                LDMX4P(b[2], b[3], bBu + bj * BPL + boff2);
                LDMX2(b[4],        bBu + bj * BPL + boff4);
#pragma unroll
                for (int ai = 0; ai <= 2 - bj; ai++)
#pragma unroll
                    for (int i = 0; i < 2; i++)
#pragma unroll
                        for (int j = 0; j < 5; j++)
                            mma16816(acc[i][j], afr[ai][i], b[j]);
            }
        }

        if (ch < NCH - 1) {
            char* aN = dsm + (s ^ 1) * STAGE;
#pragma unroll
            for (int i = 0; i < 2; i++) storeA(aN, t + NTHR * i, pf[i]);
            CP_WAIT0();
        }
        __syncthreads();
    }

    // ---- stage logits (+bias) to smem ----
    float* L = (float*)dsm;
#pragma unroll
    for (int i = 0; i < 2; i++)
#pragma unroll
        for (int j = 0; j < 5; j++) {
            const int r0 = wm * 32 + i * 16 + gID;
            const int c0 = wn * 40 + j * 8 + tid4 * 2;
            L[r0 * LP + c0]           = acc[i][j][0] + bias_s[c0];
            L[r0 * LP + c0 + 1]       = acc[i][j][1] + bias_s[c0 + 1];
            L[(r0 + 8) * LP + c0]     = acc[i][j][2] + bias_s[c0];
            L[(r0 + 8) * LP + c0 + 1] = acc[i][j][3] + bias_s[c0 + 1];
        }
    __syncthreads();

    // ---- softmax + argmax: 2 threads per row (39 cols each) ----
    {
        const int r = t >> 1, h = t & 1;
        const int cb = h * 39;
        float mx = -1e30f; int am = 127;
        for (int c = 0; c < 39; c++) {
            float v = L[r * LP + cb + c];
            if (v > mx) { mx = v; am = cb + c; }
        }
        float omx = __shfl_xor_sync(0xFFFFFFFFu, mx, 1);
        int   oam = __shfl_xor_sync(0xFFFFFFFFu, am, 1);
        if (omx > mx || (omx == mx && oam < am)) { mx = omx; am = oam; }
        float ssum = 0.0f;
        for (int c = 0; c < 39; c++) {
            float e = __expf(L[r * LP + cb + c] - mx);
            L[r * LP + cb + c] = e;
            ssum += e;
        }
        ssum += __shfl_xor_sync(0xFFFFFFFFu, ssum, 1);
        if (h == 0) {
            rinv_s[r] = __frcp_rn(ssum);
            g_best[m0 + r] = am;
        }
    }
    __syncthreads();

    // ---- coalesced softmax prob writes ----
    for (int idx = t; idx < RT * Cc; idx += NTHR) {
        const int r = idx / Cc, c = idx - r * Cc;
        out[(size_t)(m0 + r) * Cc + c] = L[r * LP + c] * rinv_s[r];
    }
}

// ---------------- CTC greedy collapse (warp-ballot, proven) ----------------
__global__ __launch_bounds__(256)
void decode_kernel(float* __restrict__ out, size_t out_elems)
{
    const int warp = (blockIdx.x * blockDim.x + threadIdx.x) >> 5;
    const int lane = threadIdx.x & 31;
    if (warp >= Bsz) return;

    size_t obase = LOGITS_ELEMS + (size_t)warp * PRED;
    if (obase + PRED > out_elems) return;
    float* lab = out + obase;

    if (lane < PRED) lab[lane] = -1.0f;
    __syncwarp();

    const int* row = g_best + (size_t)warp * Tlen;
    int prefix = 0;
    int carry  = -1;
#pragma unroll
    for (int seg = 0; seg < 3; seg++) {
        const int idx = seg * 32 + lane;
        const bool valid = (idx < Tlen);
        int v = valid ? row[idx] : BLANKI;
        int prev = __shfl_up_sync(0xFFFFFFFFu, v, 1);
        if (lane == 0) prev = carry;
        const bool keep = valid && (v != BLANKI) && (v != prev);
        const unsigned mask = __ballot_sync(0xFFFFFFFFu, keep);
        const int pos = prefix + __popc(mask & ((1u << lane) - 1u));
        if (keep && pos < PRED) lab[pos] = (float)v;
        prefix += __popc(mask);
        carry = __shfl_sync(0xFFFFFFFFu, v, 31);
    }
}

// ---------------- launch ----------------
extern "C" void kernel_launch(void* const* d_in, const int* in_sizes, int n_in,
                              void* d_out, int out_size)
{
    const float* feat = (const float*)d_in[0];  // [1024,80,512]
    const float* Wm   = (const float*)d_in[1];  // [512,78]
    const float* bias = (const float*)d_in[2];  // [78]
    float* out = (float*)d_out;

    cudaFuncSetAttribute(gemm_mma_kernel,
                         cudaFuncAttributeMaxDynamicSharedMemorySize, SMEM_BYTES);

    prep_w<<<(80 * Dd + 255) / 256, 256>>>(Wm);
    gemm_mma_kernel<<<Mrows / RT, NTHR, SMEM_BYTES>>>(feat, bias, out);
    decode_kernel<<<(Bsz * 32) / 256, 256>>>(out, (size_t)out_size);
}

// round 12
// speedup vs baseline: 1.1386x; 1.1386x over previous
#include <cuda_runtime.h>
#include <cuda_bf16.h>
#include <cstdint>
#include <math.h>

// ---------------- problem constants ----------------
#define Bsz   1024
#define Tlen  80
#define Dd    512
#define Cc    78
#define Mrows (Bsz*Tlen)          // 81920
#define BLANKI 77
#define PRED  30
#define LOGITS_ELEMS ((size_t)Mrows * Cc)

// ---------------- tiling ----------------
#define RT    128                 // rows per CTA
#define NTHR  256                 // 8 warps: 4 m-warps x 2 n-warps
#define BK    16                  // K per chunk (1 mma k-step)
#define NCH   (Dd/BK)             // 32 chunks
#define AROW  24                  // bf16 row stride (16 data + 8 pad; 48B)
#define BROW  24
#define APL   (RT*AROW*2)         // A limb plane bytes = 6144
#define BPL   (80*BROW*2)         // B limb plane bytes = 3840
#define BOFF  (3*APL)             // 18432
#define LSTG  (BOFF + 3*BPL)      // limb stage = 29952
#define RAW_OFF (2*LSTG)          // 59904
#define RAWPL (RT*BK*4)           // raw fp32 A plane = 8192 (row stride 64B)
#define SMEM_BYTES (RAW_OFF + 2*RAWPL)   // 76288 -> 3 CTAs/SM fits carveout
#define LP    84                  // epilogue logits row stride (floats)
#define RINV_OFF 10752            // float offset of rinv in dsm (after L: 128*84=10752)

// ---------------- device scratch (static, no runtime alloc) ----------------
__device__ int  g_best[Mrows];
__device__ __nv_bfloat16 g_Ws[3][80][Dd];   // W^T limbs: [limb][n][k]

// ---------------- helpers ----------------
__device__ __forceinline__ void split3(float v, __nv_bfloat16& h0,
                                       __nv_bfloat16& h1, __nv_bfloat16& h2) {
    h0 = __float2bfloat16_rn(v);
    float r1 = v - __bfloat162float(h0);
    h1 = __float2bfloat16_rn(r1);
    float r2 = r1 - __bfloat162float(h1);
    h2 = __float2bfloat16_rn(r2);
}

__device__ __forceinline__ void split3x2(float x, float y,
                                         uint32_t& p0, uint32_t& p1, uint32_t& p2) {
    __nv_bfloat162 h0 = __float22bfloat162_rn(make_float2(x, y));
    float2 f0 = __bfloat1622float2(h0);
    float rx = x - f0.x, ry = y - f0.y;
    __nv_bfloat162 h1 = __float22bfloat162_rn(make_float2(rx, ry));
    float2 f1 = __bfloat1622float2(h1);
    __nv_bfloat162 h2 = __float22bfloat162_rn(make_float2(rx - f1.x, ry - f1.y));
    p0 = *reinterpret_cast<uint32_t*>(&h0);
    p1 = *reinterpret_cast<uint32_t*>(&h1);
    p2 = *reinterpret_cast<uint32_t*>(&h2);
}

__device__ __forceinline__ void mma16816(float c[4], const uint32_t a[4],
                                         const uint32_t b[2]) {
    asm volatile(
        "mma.sync.aligned.m16n8k16.row.col.f32.bf16.bf16.f32 "
        "{%0,%1,%2,%3}, {%4,%5,%6,%7}, {%8,%9}, {%0,%1,%2,%3};"
        : "+f"(c[0]), "+f"(c[1]), "+f"(c[2]), "+f"(c[3])
        : "r"(a[0]), "r"(a[1]), "r"(a[2]), "r"(a[3]), "r"(b[0]), "r"(b[1]));
}

#define LDMX4(r, addr) \
    asm volatile("ldmatrix.sync.aligned.m8n8.x4.shared.b16 {%0,%1,%2,%3}, [%4];" \
        : "=r"((r)[0]), "=r"((r)[1]), "=r"((r)[2]), "=r"((r)[3]) : "r"(addr))
#define LDMX4P(r0, r1, addr) \
    asm volatile("ldmatrix.sync.aligned.m8n8.x4.shared.b16 {%0,%1,%2,%3}, [%4];" \
        : "=r"((r0)[0]), "=r"((r0)[1]), "=r"((r1)[0]), "=r"((r1)[1]) : "r"(addr))
#define LDMX2(r, addr) \
    asm volatile("ldmatrix.sync.aligned.m8n8.x2.shared.b16 {%0,%1}, [%2];" \
        : "=r"((r)[0]), "=r"((r)[1]) : "r"(addr))

__device__ __forceinline__ void cp_async16(uint32_t dst_smem, const void* src) {
    asm volatile("cp.async.cg.shared.global [%0], [%1], 16;" :: "r"(dst_smem), "l"(src));
}
#define CP_COMMIT() asm volatile("cp.async.commit_group;" ::: "memory")
#define CP_WAIT0()  asm volatile("cp.async.wait_group 0;" ::: "memory")

// ---------------- W prep: transpose + 3-way bf16 split ----------------
__global__ void prep_w(const float* __restrict__ Wm) {
    int i = blockIdx.x * blockDim.x + threadIdx.x;   // n*512 + k
    if (i >= 80 * Dd) return;
    int n = i >> 9, k = i & 511;
    float v = (n < Cc) ? Wm[(size_t)k * Cc + n] : 0.0f;
    __nv_bfloat16 h0, h1, h2;
    split3(v, h0, h1, h2);
    g_Ws[0][n][k] = h0; g_Ws[1][n][k] = h1; g_Ws[2][n][k] = h2;
}

// ---------------- fused mma GEMM + softmax + argmax ----------------
// CTA tile 128x80, 8 warps as (wm 0..3) x (wn 0..1): warp tile 32x40.
// Raw A staged via cp.async (fp32), split to 3 bf16 limb planes after compute.
// Per chunk: one k16-step of 6 limb passes {a0b0,a1b0,a2b0,a0b1,a1b1,a0b2}.
__global__ __launch_bounds__(NTHR, 3)
void gemm_mma_kernel(const float* __restrict__ feat,
                     const float* __restrict__ bias,
                     float* __restrict__ out)
{
    extern __shared__ char dsm[];

    const int t    = threadIdx.x;
    const int lane = t & 31;
    const int wid  = t >> 5;
    const int wm   = wid & 3;
    const int wn   = wid >> 2;
    const int gID  = lane >> 2;
    const int tid4 = lane & 3;
    const int m0   = blockIdx.x * RT;
    const uint32_t dsmu = (uint32_t)__cvta_generic_to_shared(dsm);

    // ldmatrix per-lane address offsets (within plane)
    const uint32_t aoff0 = (uint32_t)((wm * 32 + (lane & 15)) * (AROW * 2) + (lane >> 4) * 16);
    const uint32_t aoff1 = aoff0 + 16 * (AROW * 2);
    const uint32_t boff0 = (uint32_t)((wn * 40 + (lane >> 4) * 8 + (lane & 7)) * (BROW * 2)
                                      + ((lane >> 3) & 1) * 16);
    const uint32_t boff2 = boff0 + 16 * (BROW * 2);
    const uint32_t boff4 = (uint32_t)((wn * 40 + 32 + (lane & 7)) * (BROW * 2)
                                      + ((lane >> 3) & 1) * 16);

    float acc[2][5][4];
#pragma unroll
    for (int i = 0; i < 2; i++)
#pragma unroll
        for (int j = 0; j < 5; j++)
#pragma unroll
            for (int q = 0; q < 4; q++) acc[i][j][q] = 0.0f;

    const float* featb = feat + (size_t)m0 * Dd;

    // ---- cp.async issuers ----
    auto issueRawA = [&](int stage, int kb) {
        const uint32_t ru = dsmu + RAW_OFF + stage * RAWPL;
#pragma unroll
        for (int i = 0; i < 2; i++) {
            const int idx = t + NTHR * i;            // 0..511
            const int r = idx >> 2, q = idx & 3;
            cp_async16(ru + r * 64 + q * 16, featb + (size_t)r * Dd + kb + q * 4);
        }
    };
    auto issueB = [&](int stage, int kb) {
        const uint32_t bu = dsmu + stage * LSTG + BOFF;
#pragma unroll
        for (int i = 0; i < 2; i++) {
            const int idx = t + NTHR * i;            // 0..511, use 0..479
            if (idx < 480) {
                const int p = idx / 160, rem = idx - p * 160;
                const int n = rem >> 1, q = rem & 1;
                cp_async16(bu + p * BPL + n * (BROW * 2) + q * 16,
                           &g_Ws[p][n][kb + q * 8]);
            }
        }
    };
    // ---- split raw A (self-written bytes) into limb planes ----
    auto splitA = [&](int stage) {
        const char* raw = dsm + RAW_OFF + stage * RAWPL;
        char* aB = dsm + stage * LSTG;
#pragma unroll
        for (int i = 0; i < 2; i++) {
            const int idx = t + NTHR * i;            // 0..511
            const int r = idx >> 2, q = idx & 3;
            float4 v = *reinterpret_cast<const float4*>(raw + r * 64 + q * 16);
            const int off = r * (AROW * 2) + q * 8;
            uint2 u0, u1, u2;
            split3x2(v.x, v.y, u0.x, u1.x, u2.x);
            split3x2(v.z, v.w, u0.y, u1.y, u2.y);
            *(uint2*)(aB + 0 * APL + off) = u0;
            *(uint2*)(aB + 1 * APL + off) = u1;
            *(uint2*)(aB + 2 * APL + off) = u2;
        }
    };

    // ---- prologue ----
    issueRawA(0, 0);
    CP_COMMIT();
    issueRawA(1, BK);
    issueB(0, 0);
    CP_COMMIT();
    CP_WAIT0();
    splitA(0);
    __syncthreads();

    // ---- main loop: 32 chunks, 1 sync each ----
    for (int ch = 0; ch < NCH; ++ch) {
        const int s = ch & 1;
        const uint32_t aBu = dsmu + s * LSTG;
        const uint32_t bBu = aBu + BOFF;

        // issue next group: rawA(ch+2) -> raw[s], B(ch+1) -> limb[s^1].B
        if (ch + 2 < NCH) issueRawA(s, (ch + 2) * BK);
        if (ch + 1 < NCH) {
            issueB(s ^ 1, (ch + 1) * BK);
            CP_COMMIT();
        }

        // ---- compute: one k16-step, 6 limb passes ----
        {
            uint32_t afr[3][2][4];
#pragma unroll
            for (int ai = 0; ai < 3; ai++) {
                LDMX4(afr[ai][0], aBu + ai * APL + aoff0);
                LDMX4(afr[ai][1], aBu + ai * APL + aoff1);
            }
#pragma unroll
            for (int bj = 0; bj < 3; bj++) {
                const uint32_t bb = bBu + bj * BPL;
                uint32_t b0[2], b1[2];
                LDMX4P(b0, b1, bb + boff0);
#pragma unroll
                for (int ai = 0; ai < 3; ai++)
                    if (ai <= 2 - bj)
#pragma unroll
                        for (int i = 0; i < 2; i++) {
                            mma16816(acc[i][0], afr[ai][i], b0);
                            mma16816(acc[i][1], afr[ai][i], b1);
                        }
                LDMX4P(b0, b1, bb + boff2);
#pragma unroll
                for (int ai = 0; ai < 3; ai++)
                    if (ai <= 2 - bj)
#pragma unroll
                        for (int i = 0; i < 2; i++) {
                            mma16816(acc[i][2], afr[ai][i], b0);
                            mma16816(acc[i][3], afr[ai][i], b1);
                        }
                LDMX2(b0, bb + boff4);
#pragma unroll
                for (int ai = 0; ai < 3; ai++)
                    if (ai <= 2 - bj)
#pragma unroll
                        for (int i = 0; i < 2; i++)
                            mma16816(acc[i][4], afr[ai][i], b0);
            }
        }

        CP_WAIT0();                      // rawA(ch+1) + B(ch+1) landed
        if (ch + 1 < NCH) splitA(s ^ 1); // limb[s^1].A for next chunk
        __syncthreads();
    }

    // ---- stage logits (+bias via L2) to smem ----
    float* L = (float*)dsm;
    float* rinv_s = (float*)dsm + RINV_OFF;
#pragma unroll
    for (int i = 0; i < 2; i++)
#pragma unroll
        for (int j = 0; j < 5; j++) {
            const int r0 = wm * 32 + i * 16 + gID;
            const int c0 = wn * 40 + j * 8 + tid4 * 2;
            const float b0 = __ldg(bias + c0);
            const float b1 = (c0 + 1 < Cc) ? __ldg(bias + c0 + 1) : 0.0f;
            L[r0 * LP + c0]           = acc[i][j][0] + b0;
            L[r0 * LP + c0 + 1]       = acc[i][j][1] + b1;
            L[(r0 + 8) * LP + c0]     = acc[i][j][2] + b0;
            L[(r0 + 8) * LP + c0 + 1] = acc[i][j][3] + b1;
        }
    __syncthreads();

    // ---- softmax + argmax: 2 threads per row (39 cols each) ----
    {
        const int r = t >> 1, h = t & 1;
        const int cb = h * 39;
        float mx = -1e30f; int am = 127;
        for (int c = 0; c < 39; c++) {
            float v = L[r * LP + cb + c];
            if (v > mx) { mx = v; am = cb + c; }
        }
        float omx = __shfl_xor_sync(0xFFFFFFFFu, mx, 1);
        int   oam = __shfl_xor_sync(0xFFFFFFFFu, am, 1);
        if (omx > mx || (omx == mx && oam < am)) { mx = omx; am = oam; }
        float ssum = 0.0f;
        for (int c = 0; c < 39; c++) {
            float e = __expf(L[r * LP + cb + c] - mx);
            L[r * LP + cb + c] = e;
            ssum += e;
        }
        ssum += __shfl_xor_sync(0xFFFFFFFFu, ssum, 1);
        if (h == 0) {
            rinv_s[r] = __frcp_rn(ssum);
            g_best[m0 + r] = am;
        }
    }
    __syncthreads();

    // ---- coalesced softmax prob writes ----
    for (int idx = t; idx < RT * Cc; idx += NTHR) {
        const int r = idx / Cc, c = idx - r * Cc;
        out[(size_t)(m0 + r) * Cc + c] = L[r * LP + c] * rinv_s[r];
    }
}

// ---------------- CTC greedy collapse (warp-ballot, proven) ----------------
__global__ __launch_bounds__(256)
void decode_kernel(float* __restrict__ out, size_t out_elems)
{
    const int warp = (blockIdx.x * blockDim.x + threadIdx.x) >> 5;
    const int lane = threadIdx.x & 31;
    if (warp >= Bsz) return;

    size_t obase = LOGITS_ELEMS + (size_t)warp * PRED;
    if (obase + PRED > out_elems) return;
    float* lab = out + obase;

    if (lane < PRED) lab[lane] = -1.0f;
    __syncwarp();

    const int* row = g_best + (size_t)warp * Tlen;
    int prefix = 0;
    int carry  = -1;
#pragma unroll
    for (int seg = 0; seg < 3; seg++) {
        const int idx = seg * 32 + lane;
        const bool valid = (idx < Tlen);
        int v = valid ? row[idx] : BLANKI;
        int prev = __shfl_up_sync(0xFFFFFFFFu, v, 1);
        if (lane == 0) prev = carry;
        const bool keep = valid && (v != BLANKI) && (v != prev);
        const unsigned mask = __ballot_sync(0xFFFFFFFFu, keep);
        const int pos = prefix + __popc(mask & ((1u << lane) - 1u));
        if (keep && pos < PRED) lab[pos] = (float)v;
        prefix += __popc(mask);
        carry = __shfl_sync(0xFFFFFFFFu, v, 31);
    }
}

// ---------------- launch ----------------
extern "C" void kernel_launch(void* const* d_in, const int* in_sizes, int n_in,
                              void* d_out, int out_size)
{
    const float* feat = (const float*)d_in[0];  // [1024,80,512]
    const float* Wm   = (const float*)d_in[1];  // [512,78]
    const float* bias = (const float*)d_in[2];  // [78]
    float* out = (float*)d_out;

    cudaFuncSetAttribute(gemm_mma_kernel,
                         cudaFuncAttributeMaxDynamicSharedMemorySize, SMEM_BYTES);

    prep_w<<<(80 * Dd + 255) / 256, 256>>>(Wm);
    gemm_mma_kernel<<<Mrows / RT, NTHR, SMEM_BYTES>>>(feat, bias, out);
    decode_kernel<<<(Bsz * 32) / 256, 256>>>(out, (size_t)out_size);
}

// round 13
// speedup vs baseline: 2.0599x; 1.8092x over previous
#include <cuda_runtime.h>
#include <cuda_fp16.h>
#include <cstdint>
#include <math.h>

// ---------------- problem constants ----------------
#define Bsz   1024
#define Tlen  80
#define Dd    512
#define Cc    78
#define Mrows (Bsz*Tlen)          // 81920
#define BLANKI 77
#define PRED  30
#define LOGITS_ELEMS ((size_t)Mrows * Cc)

// ---------------- tiling (R7-proven shape, 2 fp16 limb planes) ----------------
#define BK    32                  // K per chunk (2 mma k-steps)
#define NCH   (Dd/BK)             // 16 chunks
#define AROW  40                  // fp16 row stride (32 data + 8 pad; 80B, 16B-aligned)
#define BROW  40
#define APL   (128*AROW*2)        // A plane bytes = 10240
#define BPL   (80*BROW*2)         // B plane bytes = 6400
#define BOFF  (2*APL)             // 20480
#define STAGE (BOFF + 2*BPL)      // 33280
#define SMEM_BYTES (2*STAGE)      // 66560 (>= 128*84*4 = 43008 epilogue bytes)
#define LP    84                  // epilogue logits row stride (floats)

// ---------------- device scratch (static, no runtime alloc) ----------------
__device__ int    g_best[Mrows];
__device__ __half g_Ws[2][80][Dd];   // W^T fp16 limbs: [limb][n][k]

// ---------------- helpers ----------------
// paired fp16 2-limb split: (x,y) -> 2 packed half2 limbs
__device__ __forceinline__ void split2x2(float x, float y,
                                         uint32_t& p0, uint32_t& p1) {
    __half2 h0 = __float22half2_rn(make_float2(x, y));
    float2 f0 = __half22float2(h0);
    __half2 h1 = __float22half2_rn(make_float2(x - f0.x, y - f0.y));
    p0 = *reinterpret_cast<uint32_t*>(&h0);
    p1 = *reinterpret_cast<uint32_t*>(&h1);
}

__device__ __forceinline__ void mma16816(float c[4], const uint32_t a[4],
                                         const uint32_t b[2]) {
    asm volatile(
        "mma.sync.aligned.m16n8k16.row.col.f32.f16.f16.f32 "
        "{%0,%1,%2,%3}, {%4,%5,%6,%7}, {%8,%9}, {%0,%1,%2,%3};"
        : "+f"(c[0]), "+f"(c[1]), "+f"(c[2]), "+f"(c[3])
        : "r"(a[0]), "r"(a[1]), "r"(a[2]), "r"(a[3]), "r"(b[0]), "r"(b[1]));
}

#define LDMX4(r, addr) \
    asm volatile("ldmatrix.sync.aligned.m8n8.x4.shared.b16 {%0,%1,%2,%3}, [%4];" \
        : "=r"((r)[0]), "=r"((r)[1]), "=r"((r)[2]), "=r"((r)[3]) : "r"(addr))
#define LDMX4P(r0, r1, addr) \
    asm volatile("ldmatrix.sync.aligned.m8n8.x4.shared.b16 {%0,%1,%2,%3}, [%4];" \
        : "=r"((r0)[0]), "=r"((r0)[1]), "=r"((r1)[0]), "=r"((r1)[1]) : "r"(addr))
#define LDMX2(r, addr) \
    asm volatile("ldmatrix.sync.aligned.m8n8.x2.shared.b16 {%0,%1}, [%2];" \
        : "=r"((r)[0]), "=r"((r)[1]) : "r"(addr))

__device__ __forceinline__ void cp_async16(uint32_t dst_smem, const void* src) {
    asm volatile("cp.async.cg.shared.global [%0], [%1], 16;" :: "r"(dst_smem), "l"(src));
}
#define CP_COMMIT() asm volatile("cp.async.commit_group;" ::: "memory")
#define CP_WAIT0()  asm volatile("cp.async.wait_group 0;" ::: "memory")

// ---------------- W prep: transpose + 2-way fp16 split ----------------
__global__ void prep_w(const float* __restrict__ Wm) {
    int i = blockIdx.x * blockDim.x + threadIdx.x;   // n*512 + k
    if (i >= 80 * Dd) return;
    int n = i >> 9, k = i & 511;
    float v = (n < Cc) ? Wm[(size_t)k * Cc + n] : 0.0f;
    __half h0 = __float2half_rn(v);
    __half h1 = __float2half_rn(v - __half2float(h0));
    g_Ws[0][n][k] = h0;
    g_Ws[1][n][k] = h1;
}

// ---------------- fused mma GEMM + softmax + argmax ----------------
// CTA tile 128x80, 8 warps as (wm 0..3) x (wn 0..1): warp tile 32x40.
// Per k16-step: 3 limb passes {a0b0, a1b0, a0b1} (a1b1 ~2^-22, dropped).
__global__ __launch_bounds__(256, 2)
void gemm_mma_kernel(const float* __restrict__ feat,
                     const float* __restrict__ bias,
                     float* __restrict__ out)
{
    extern __shared__ char dsm[];
    __shared__ float bias_s[80];
    __shared__ float rinv_s[128];

    const int t    = threadIdx.x;
    const int lane = t & 31;
    const int wid  = t >> 5;
    const int wm   = wid & 3;
    const int wn   = wid >> 2;
    const int gID  = lane >> 2;
    const int tid4 = lane & 3;
    const int m0   = blockIdx.x * 128;
    const uint32_t dsmu = (uint32_t)__cvta_generic_to_shared(dsm);

    if (t < 80) bias_s[t] = (t < Cc) ? bias[t] : 0.0f;

    // ldmatrix per-lane address offsets (within plane)
    const uint32_t aoff0 = (uint32_t)((wm * 32 + (lane & 15)) * (AROW * 2) + (lane >> 4) * 16);
    const uint32_t aoff1 = aoff0 + 16 * (AROW * 2);
    const uint32_t boff0 = (uint32_t)((wn * 40 + (lane >> 4) * 8 + (lane & 7)) * (BROW * 2)
                                      + ((lane >> 3) & 1) * 16);
    const uint32_t boff2 = boff0 + 16 * (BROW * 2);
    const uint32_t boff4 = (uint32_t)((wn * 40 + 32 + (lane & 7)) * (BROW * 2)
                                      + ((lane >> 3) & 1) * 16);

    float acc[2][5][4];
#pragma unroll
    for (int i = 0; i < 2; i++)
#pragma unroll
        for (int j = 0; j < 5; j++)
#pragma unroll
            for (int q = 0; q < 4; q++) acc[i][j][q] = 0.0f;

    const float* featb = feat + (size_t)m0 * Dd;

    // ---- A store: split fp32 float4 -> 2 fp16 planes ----
    auto storeA = [&](char* aB, int fidx, float4 v) {
        const int r = fidx >> 3, q = fidx & 7;       // 8 float4 per 32-float row
        const int off = r * (AROW * 2) + q * 8;
        uint32_t p0a, p1a, p0b, p1b;
        split2x2(v.x, v.y, p0a, p1a);
        split2x2(v.z, v.w, p0b, p1b);
        *(uint32_t*)(aB + 0 * APL + off)     = p0a;
        *(uint32_t*)(aB + 0 * APL + off + 4) = p0b;
        *(uint32_t*)(aB + 1 * APL + off)     = p1a;
        *(uint32_t*)(aB + 1 * APL + off + 4) = p1b;
    };

    // ---- B load: 640 x 16B per chunk via cp.async (2 planes) ----
    auto loadB = [&](uint32_t bBu, int kb) {
#pragma unroll
        for (int i = 0; i < 3; i++) {
            const int idx = t + 256 * i;            // 0..767, use 0..639
            if (idx < 640) {
                const int p = idx / 320, rem = idx - p * 320;
                const int n = rem >> 2, q = rem & 3;
                cp_async16(bBu + p * BPL + n * (BROW * 2) + q * 16,
                           &g_Ws[p][n][kb + q * 8]);
            }
        }
    };

    // ---- prologue: chunk 0 ----
    {
        loadB(dsmu + BOFF, 0);
        CP_COMMIT();
#pragma unroll
        for (int i = 0; i < 4; i++) {
            const int fidx = t + 256 * i;           // 0..1023
            const int r = fidx >> 3, q = fidx & 7;
            float4 v = *reinterpret_cast<const float4*>(featb + (size_t)r * Dd + q * 4);
            storeA(dsm, fidx, v);
        }
        CP_WAIT0();
    }
    __syncthreads();

    // ---- main loop: 16 chunks ----
    for (int ch = 0; ch < NCH; ++ch) {
        const int s = ch & 1;
        const uint32_t aBu = dsmu + s * STAGE;
        const uint32_t bBu = aBu + BOFF;

        float4 pf[4];
        if (ch < NCH - 1) {
            const int kb = (ch + 1) * BK;
#pragma unroll
            for (int i = 0; i < 4; i++) {
                const int fidx = t + 256 * i;
                const int r = fidx >> 3, q = fidx & 7;
                pf[i] = *reinterpret_cast<const float4*>(featb + (size_t)r * Dd + kb + q * 4);
            }
            loadB(dsmu + (s ^ 1) * STAGE + BOFF, kb);
            CP_COMMIT();
        }

        // ---- 2 k-steps of 3-pass fp16 limb mma (ldmatrix fragments) ----
#pragma unroll
        for (int k0 = 0; k0 < 2; k0++) {
            const uint32_t kb = k0 * 32;            // 16 fp16 = 32 bytes
            uint32_t afr[2][2][4];
#pragma unroll
            for (int ai = 0; ai < 2; ai++) {
                LDMX4(afr[ai][0], aBu + ai * APL + aoff0 + kb);
                LDMX4(afr[ai][1], aBu + ai * APL + aoff1 + kb);
            }
#pragma unroll
            for (int bj = 0; bj < 2; bj++) {
                uint32_t b[5][2];
                LDMX4P(b[0], b[1], bBu + bj * BPL + boff0 + kb);
                LDMX4P(b[2], b[3], bBu + bj * BPL + boff2 + kb);
                LDMX2(b[4],        bBu + bj * BPL + boff4 + kb);
#pragma unroll
                for (int ai = 0; ai <= 1 - bj; ai++)
#pragma unroll
                    for (int i = 0; i < 2; i++)
#pragma unroll
                        for (int j = 0; j < 5; j++)
                            mma16816(acc[i][j], afr[ai][i], b[j]);
            }
        }

        if (ch < NCH - 1) {
            char* aN = dsm + (s ^ 1) * STAGE;
#pragma unroll
            for (int i = 0; i < 4; i++) storeA(aN, t + 256 * i, pf[i]);
            CP_WAIT0();
        }
        __syncthreads();
    }

    // ---- stage logits (+bias) to smem ----
    float* L = (float*)dsm;
#pragma unroll
    for (int i = 0; i < 2; i++)
#pragma unroll
        for (int j = 0; j < 5; j++) {
            const int r0 = wm * 32 + i * 16 + gID;
            const int c0 = wn * 40 + j * 8 + tid4 * 2;
            L[r0 * LP + c0]           = acc[i][j][0] + bias_s[c0];
            L[r0 * LP + c0 + 1]       = acc[i][j][1] + bias_s[c0 + 1];
            L[(r0 + 8) * LP + c0]     = acc[i][j][2] + bias_s[c0];
            L[(r0 + 8) * LP + c0 + 1] = acc[i][j][3] + bias_s[c0 + 1];
        }
    __syncthreads();

    // ---- softmax + argmax: 2 threads per row (39 cols each) ----
    {
        const int r = t >> 1, h = t & 1;
        const int cb = h * 39;
        float mx = -1e30f; int am = 127;
        for (int c = 0; c < 39; c++) {
            float v = L[r * LP + cb + c];
            if (v > mx) { mx = v; am = cb + c; }
        }
        float omx = __shfl_xor_sync(0xFFFFFFFFu, mx, 1);
        int   oam = __shfl_xor_sync(0xFFFFFFFFu, am, 1);
        if (omx > mx || (omx == mx && oam < am)) { mx = omx; am = oam; }
        float ssum = 0.0f;
        for (int c = 0; c < 39; c++) {
            float e = __expf(L[r * LP + cb + c] - mx);
            L[r * LP + cb + c] = e;
            ssum += e;
        }
        ssum += __shfl_xor_sync(0xFFFFFFFFu, ssum, 1);
        if (h == 0) {
            rinv_s[r] = __frcp_rn(ssum);
            g_best[m0 + r] = am;
        }
    }
    __syncthreads();

    // ---- coalesced softmax prob writes ----
    for (int idx = t; idx < 128 * Cc; idx += 256) {
        const int r = idx / Cc, c = idx - r * Cc;
        out[(size_t)(m0 + r) * Cc + c] = L[r * LP + c] * rinv_s[r];
    }
}

// ---------------- CTC greedy collapse (warp-ballot, proven) ----------------
__global__ __launch_bounds__(256)
void decode_kernel(float* __restrict__ out, size_t out_elems)
{
    const int warp = (blockIdx.x * blockDim.x + threadIdx.x) >> 5;
    const int lane = threadIdx.x & 31;
    if (warp >= Bsz) return;

    size_t obase = LOGITS_ELEMS + (size_t)warp * PRED;
    if (obase + PRED > out_elems) return;
    float* lab = out + obase;

    if (lane < PRED) lab[lane] = -1.0f;
    __syncwarp();

    const int* row = g_best + (size_t)warp * Tlen;
    int prefix = 0;
    int carry  = -1;
#pragma unroll
    for (int seg = 0; seg < 3; seg++) {
        const int idx = seg * 32 + lane;
        const bool valid = (idx < Tlen);
        int v = valid ? row[idx] : BLANKI;
        int prev = __shfl_up_sync(0xFFFFFFFFu, v, 1);
        if (lane == 0) prev = carry;
        const bool keep = valid && (v != BLANKI) && (v != prev);
        const unsigned mask = __ballot_sync(0xFFFFFFFFu, keep);
        const int pos = prefix + __popc(mask & ((1u << lane) - 1u));
        if (keep && pos < PRED) lab[pos] = (float)v;
        prefix += __popc(mask);
        carry = __shfl_sync(0xFFFFFFFFu, v, 31);
    }
}

// ---------------- launch ----------------
extern "C" void kernel_launch(void* const* d_in, const int* in_sizes, int n_in,
                              void* d_out, int out_size)
{
    const float* feat = (const float*)d_in[0];  // [1024,80,512]
    const float* Wm   = (const float*)d_in[1];  // [512,78]
    const float* bias = (const float*)d_in[2];  // [78]
    float* out = (float*)d_out;

    cudaFuncSetAttribute(gemm_mma_kernel,
                         cudaFuncAttributeMaxDynamicSharedMemorySize, SMEM_BYTES);

    prep_w<<<(80 * Dd + 255) / 256, 256>>>(Wm);
    gemm_mma_kernel<<<Mrows / 128, 256, SMEM_BYTES>>>(feat, bias, out);
    decode_kernel<<<(Bsz * 32) / 256, 256>>>(out, (size_t)out_size);
}

// round 14
// speedup vs baseline: 2.0607x; 1.0004x over previous
#include <cuda_runtime.h>
#include <cuda_fp16.h>
#include <cstdint>
#include <math.h>

// ---------------- problem constants ----------------
#define Bsz   1024
#define Tlen  80
#define Dd    512
#define Cc    78
#define Mrows (Bsz*Tlen)          // 81920
#define BLANKI 77
#define PRED  30
#define LOGITS_ELEMS ((size_t)Mrows * Cc)

// ---------------- tiling (fp16 2-limb, 160-row tiles = 2 batch elems) ----------------
#define RT    160                 // rows per CTA
#define NTHR  320                 // 10 warps: 5 m-warps x 2 n-warps
#define BK    32                  // K per chunk (2 mma k-steps)
#define NCH   (Dd/BK)             // 16 chunks
#define AROW  40                  // fp16 row stride (32 data + 8 pad; 80B, 16B-aligned)
#define BROW  40
#define APL   (RT*AROW*2)         // A plane bytes = 12800
#define BPL   (80*BROW*2)         // B plane bytes = 6400
#define BOFF  (2*APL)             // 25600
#define STAGE (BOFF + 2*BPL)      // 38400
#define SMEM_BYTES (2*STAGE)      // 76800 (>= 160*84*4 = 53760 epilogue bytes); 2 CTAs/SM
#define LP    84                  // epilogue logits row stride (floats)

// ---------------- device scratch (static, no runtime alloc) ----------------
__device__ __half g_Ws[2][80][Dd];   // W^T fp16 limbs: [limb][n][k]

// ---------------- helpers ----------------
// paired fp16 2-limb split: (x,y) -> 2 packed half2 limbs
__device__ __forceinline__ void split2x2(float x, float y,
                                         uint32_t& p0, uint32_t& p1) {
    __half2 h0 = __float22half2_rn(make_float2(x, y));
    float2 f0 = __half22float2(h0);
    __half2 h1 = __float22half2_rn(make_float2(x - f0.x, y - f0.y));
    p0 = *reinterpret_cast<uint32_t*>(&h0);
    p1 = *reinterpret_cast<uint32_t*>(&h1);
}

__device__ __forceinline__ void mma16816(float c[4], const uint32_t a[4],
                                         const uint32_t b[2]) {
    asm volatile(
        "mma.sync.aligned.m16n8k16.row.col.f32.f16.f16.f32 "
        "{%0,%1,%2,%3}, {%4,%5,%6,%7}, {%8,%9}, {%0,%1,%2,%3};"
        : "+f"(c[0]), "+f"(c[1]), "+f"(c[2]), "+f"(c[3])
        : "r"(a[0]), "r"(a[1]), "r"(a[2]), "r"(a[3]), "r"(b[0]), "r"(b[1]));
}

#define LDMX4(r, addr) \
    asm volatile("ldmatrix.sync.aligned.m8n8.x4.shared.b16 {%0,%1,%2,%3}, [%4];" \
        : "=r"((r)[0]), "=r"((r)[1]), "=r"((r)[2]), "=r"((r)[3]) : "r"(addr))
#define LDMX4P(r0, r1, addr) \
    asm volatile("ldmatrix.sync.aligned.m8n8.x4.shared.b16 {%0,%1,%2,%3}, [%4];" \
        : "=r"((r0)[0]), "=r"((r0)[1]), "=r"((r1)[0]), "=r"((r1)[1]) : "r"(addr))
#define LDMX2(r, addr) \
    asm volatile("ldmatrix.sync.aligned.m8n8.x2.shared.b16 {%0,%1}, [%2];" \
        : "=r"((r)[0]), "=r"((r)[1]) : "r"(addr))

__device__ __forceinline__ void cp_async16(uint32_t dst_smem, const void* src) {
    asm volatile("cp.async.cg.shared.global [%0], [%1], 16;" :: "r"(dst_smem), "l"(src));
}
#define CP_COMMIT() asm volatile("cp.async.commit_group;" ::: "memory")
#define CP_WAIT0()  asm volatile("cp.async.wait_group 0;" ::: "memory")

// ---------------- W prep: transpose + 2-way fp16 split ----------------
__global__ void prep_w(const float* __restrict__ Wm) {
    int i = blockIdx.x * blockDim.x + threadIdx.x;   // n*512 + k
    if (i >= 80 * Dd) return;
    int n = i >> 9, k = i & 511;
    float v = (n < Cc) ? Wm[(size_t)k * Cc + n] : 0.0f;
    __half h0 = __float2half_rn(v);
    __half h1 = __float2half_rn(v - __half2float(h0));
    g_Ws[0][n][k] = h0;
    g_Ws[1][n][k] = h1;
}

// ---------------- fused mma GEMM + softmax + argmax + CTC decode ----------------
// CTA tile 160x80 (= 2 batch elements), 10 warps as (wm 0..4) x (wn 0..1).
// Per k16-step: 3 limb passes {a0b0, a1b0, a0b1} (a1b1 ~2^-22, dropped).
__global__ __launch_bounds__(NTHR, 2)
void gemm_mma_kernel(const float* __restrict__ feat,
                     const float* __restrict__ bias,
                     float* __restrict__ out, size_t out_elems)
{
    extern __shared__ char dsm[];
    __shared__ float bias_s[80];
    __shared__ float rinv_s[RT];
    __shared__ int   best_s[RT];

    const int t    = threadIdx.x;
    const int lane = t & 31;
    const int wid  = t >> 5;
    const int wm   = wid % 5;
    const int wn   = wid / 5;
    const int gID  = lane >> 2;
    const int tid4 = lane & 3;
    const int m0   = blockIdx.x * RT;
    const uint32_t dsmu = (uint32_t)__cvta_generic_to_shared(dsm);

    if (t < 80) bias_s[t] = (t < Cc) ? bias[t] : 0.0f;

    // ldmatrix per-lane address offsets (within plane)
    const uint32_t aoff0 = (uint32_t)((wm * 32 + (lane & 15)) * (AROW * 2) + (lane >> 4) * 16);
    const uint32_t aoff1 = aoff0 + 16 * (AROW * 2);
    const uint32_t boff0 = (uint32_t)((wn * 40 + (lane >> 4) * 8 + (lane & 7)) * (BROW * 2)
                                      + ((lane >> 3) & 1) * 16);
    const uint32_t boff2 = boff0 + 16 * (BROW * 2);
    const uint32_t boff4 = (uint32_t)((wn * 40 + 32 + (lane & 7)) * (BROW * 2)
                                      + ((lane >> 3) & 1) * 16);

    float acc[2][5][4];
#pragma unroll
    for (int i = 0; i < 2; i++)
#pragma unroll
        for (int j = 0; j < 5; j++)
#pragma unroll
            for (int q = 0; q < 4; q++) acc[i][j][q] = 0.0f;

    const float* featb = feat + (size_t)m0 * Dd;

    // ---- A store: split fp32 float4 -> 2 fp16 planes ----
    auto storeA = [&](char* aB, int fidx, float4 v) {
        const int r = fidx >> 3, q = fidx & 7;       // 8 float4 per 32-float row
        const int off = r * (AROW * 2) + q * 8;
        uint32_t p0a, p1a, p0b, p1b;
        split2x2(v.x, v.y, p0a, p1a);
        split2x2(v.z, v.w, p0b, p1b);
        *(uint32_t*)(aB + 0 * APL + off)     = p0a;
        *(uint32_t*)(aB + 0 * APL + off + 4) = p0b;
        *(uint32_t*)(aB + 1 * APL + off)     = p1a;
        *(uint32_t*)(aB + 1 * APL + off + 4) = p1b;
    };

    // ---- B load: 640 x 16B per chunk via cp.async (2 planes) ----
    auto loadB = [&](uint32_t bBu, int kb) {
#pragma unroll
        for (int i = 0; i < 2; i++) {
            const int idx = t + NTHR * i;            // 0..639 exactly
            const int p = idx / 320, rem = idx - p * 320;
            const int n = rem >> 2, q = rem & 3;
            cp_async16(bBu + p * BPL + n * (BROW * 2) + q * 16,
                       &g_Ws[p][n][kb + q * 8]);
        }
    };

    // ---- prologue: chunk 0 ----
    {
        loadB(dsmu + BOFF, 0);
        CP_COMMIT();
#pragma unroll
        for (int i = 0; i < 4; i++) {
            const int fidx = t + NTHR * i;           // 0..1279
            const int r = fidx >> 3, q = fidx & 7;
            float4 v = *reinterpret_cast<const float4*>(featb + (size_t)r * Dd + q * 4);
            storeA(dsm, fidx, v);
        }
        CP_WAIT0();
    }
    __syncthreads();

    // ---- main loop: 16 chunks ----
    for (int ch = 0; ch < NCH; ++ch) {
        const int s = ch & 1;
        const uint32_t aBu = dsmu + s * STAGE;
        const uint32_t bBu = aBu + BOFF;

        float4 pf[4];
        if (ch < NCH - 1) {
            const int kb = (ch + 1) * BK;
#pragma unroll
            for (int i = 0; i < 4; i++) {
                const int fidx = t + NTHR * i;
                const int r = fidx >> 3, q = fidx & 7;
                pf[i] = *reinterpret_cast<const float4*>(featb + (size_t)r * Dd + kb + q * 4);
            }
            loadB(dsmu + (s ^ 1) * STAGE + BOFF, kb);
            CP_COMMIT();
        }

        // ---- 2 k-steps of 3-pass fp16 limb mma (ldmatrix fragments) ----
#pragma unroll
        for (int k0 = 0; k0 < 2; k0++) {
            const uint32_t kb = k0 * 32;            // 16 fp16 = 32 bytes
            uint32_t afr[2][2][4];
#pragma unroll
            for (int ai = 0; ai < 2; ai++) {
                LDMX4(afr[ai][0], aBu + ai * APL + aoff0 + kb);
                LDMX4(afr[ai][1], aBu + ai * APL + aoff1 + kb);
            }
#pragma unroll
            for (int bj = 0; bj < 2; bj++) {
                uint32_t b[5][2];
                LDMX4P(b[0], b[1], bBu + bj * BPL + boff0 + kb);
                LDMX4P(b[2], b[3], bBu + bj * BPL + boff2 + kb);
                LDMX2(b[4],        bBu + bj * BPL + boff4 + kb);
#pragma unroll
                for (int ai = 0; ai <= 1 - bj; ai++)
#pragma unroll
                    for (int i = 0; i < 2; i++)
#pragma unroll
                        for (int j = 0; j < 5; j++)
                            mma16816(acc[i][j], afr[ai][i], b[j]);
            }
        }

        if (ch < NCH - 1) {
            char* aN = dsm + (s ^ 1) * STAGE;
#pragma unroll
            for (int i = 0; i < 4; i++) storeA(aN, t + NTHR * i, pf[i]);
            CP_WAIT0();
        }
        __syncthreads();
    }

    // ---- stage logits (+bias) to smem ----
    float* L = (float*)dsm;
#pragma unroll
    for (int i = 0; i < 2; i++)
#pragma unroll
        for (int j = 0; j < 5; j++) {
            const int r0 = wm * 32 + i * 16 + gID;
            const int c0 = wn * 40 + j * 8 + tid4 * 2;
            L[r0 * LP + c0]           = acc[i][j][0] + bias_s[c0];
            L[r0 * LP + c0 + 1]       = acc[i][j][1] + bias_s[c0 + 1];
            L[(r0 + 8) * LP + c0]     = acc[i][j][2] + bias_s[c0];
            L[(r0 + 8) * LP + c0 + 1] = acc[i][j][3] + bias_s[c0 + 1];
        }
    __syncthreads();

    // ---- softmax + argmax: 2 threads per row (39 cols each) ----
    {
        const int r = t >> 1, h = t & 1;
        const int cb = h * 39;
        float mx = -1e30f; int am = 127;
        for (int c = 0; c < 39; c++) {
            float v = L[r * LP + cb + c];
            if (v > mx) { mx = v; am = cb + c; }
        }
        float omx = __shfl_xor_sync(0xFFFFFFFFu, mx, 1);
        int   oam = __shfl_xor_sync(0xFFFFFFFFu, am, 1);
        if (omx > mx || (omx == mx && oam < am)) { mx = omx; am = oam; }
        float ssum = 0.0f;
        for (int c = 0; c < 39; c++) {
            float e = __expf(L[r * LP + cb + c] - mx);
            L[r * LP + cb + c] = e;
            ssum += e;
        }
        ssum += __shfl_xor_sync(0xFFFFFFFFu, ssum, 1);
        if (h == 0) {
            rinv_s[r] = __frcp_rn(ssum);
            best_s[r] = am;
        }
    }
    __syncthreads();

    // ---- fused CTC decode: warps 0/1 handle the tile's 2 batch elements ----
    if (wid < 2) {
        const int batch = blockIdx.x * 2 + wid;
        size_t obase = LOGITS_ELEMS + (size_t)batch * PRED;
        if (obase + PRED <= out_elems) {
            float* lab = out + obase;
            if (lane < PRED) lab[lane] = -1.0f;
            __syncwarp();
            const int* row = best_s + wid * Tlen;
            int prefix = 0;
            int carry  = -1;
#pragma unroll
            for (int seg = 0; seg < 3; seg++) {
                const int idx = seg * 32 + lane;
                const bool valid = (idx < Tlen);
                int v = valid ? row[idx] : BLANKI;
                int prev = __shfl_up_sync(0xFFFFFFFFu, v, 1);
                if (lane == 0) prev = carry;
                const bool keep = valid && (v != BLANKI) && (v != prev);
                const unsigned mask = __ballot_sync(0xFFFFFFFFu, keep);
                const int pos = prefix + __popc(mask & ((1u << lane) - 1u));
                if (keep && pos < PRED) lab[pos] = (float)v;
                prefix += __popc(mask);
                carry = __shfl_sync(0xFFFFFFFFu, v, 31);
            }
        }
    }

    // ---- coalesced softmax prob writes ----
    for (int idx = t; idx < RT * Cc; idx += NTHR) {
        const int r = idx / Cc, c = idx - r * Cc;
        out[(size_t)(m0 + r) * Cc + c] = L[r * LP + c] * rinv_s[r];
    }
}

// ---------------- launch ----------------
extern "C" void kernel_launch(void* const* d_in, const int* in_sizes, int n_in,
                              void* d_out, int out_size)
{
    const float* feat = (const float*)d_in[0];  // [1024,80,512]
    const float* Wm   = (const float*)d_in[1];  // [512,78]
    const float* bias = (const float*)d_in[2];  // [78]
    float* out = (float*)d_out;

    cudaFuncSetAttribute(gemm_mma_kernel,
                         cudaFuncAttributeMaxDynamicSharedMemorySize, SMEM_BYTES);

    prep_w<<<(80 * Dd + 255) / 256, 256>>>(Wm);
    gemm_mma_kernel<<<Mrows / RT, NTHR, SMEM_BYTES>>>(feat, bias, out, (size_t)out_size);
}